// round 3
// baseline (speedup 1.0000x reference)
#include <cuda_runtime.h>
#include <cuda_bf16.h>
#include <cstdint>

// Problem constants
#define BB 64
#define TT 1024
#define DD 512
#define BD (BB * DD)          // 32768
#define BTD ((size_t)BB * TT * DD)

// ---------------- scratch (no allocations allowed) ----------------
__device__ float g_xp[(size_t)TT * BB * DD];   // xproj, layout [t][b][e]
__device__ float g_m [(size_t)TT * BB * DD];   // m,     layout [t][b][e]

// ---------------- f32x2 packed-FMA helpers ----------------
__device__ __forceinline__ unsigned long long fma2(unsigned long long a,
                                                   unsigned long long b,
                                                   unsigned long long c)
{
    unsigned long long d;
    asm("fma.rn.f32x2 %0, %1, %2, %3;" : "=l"(d) : "l"(a), "l"(b), "l"(c));
    return d;
}
__device__ __forceinline__ unsigned long long pack2(float lo, float hi)
{
    unsigned long long r;
    asm("mov.b64 %0, {%1, %2};" : "=l"(r) : "f"(lo), "f"(hi));
    return r;
}
__device__ __forceinline__ float2 unpack2(unsigned long long v)
{
    float2 f;
    asm("mov.b64 {%0, %1}, %2;" : "=f"(f.x), "=f"(f.y) : "l"(v));
    return f;
}

// ---------------- cluster helpers ----------------
__device__ __forceinline__ uint32_t smem_u32(const void* p)
{
    uint32_t a;
    asm("{ .reg .u64 t; cvta.to.shared.u64 t, %1; cvt.u32.u64 %0, t; }" : "=r"(a) : "l"(p));
    return a;
}
__device__ __forceinline__ uint32_t ctarank()
{
    uint32_t r;
    asm("mov.u32 %0, %%cluster_ctarank;" : "=r"(r));
    return r;
}
__device__ __forceinline__ uint32_t mapa_rank(uint32_t addr, uint32_t rank)
{
    uint32_t r;
    asm("mapa.shared::cluster.u32 %0, %1, %2;" : "=r"(r) : "r"(addr), "r"(rank));
    return r;
}
__device__ __forceinline__ void st_cluster_f32(uint32_t addr, float v)
{
    asm volatile("st.shared::cluster.f32 [%0], %1;" :: "r"(addr), "f"(v) : "memory");
}
__device__ __forceinline__ void mbar_init(uint32_t addr, uint32_t cnt)
{
    asm volatile("mbarrier.init.shared.b64 [%0], %1;" :: "r"(addr), "r"(cnt) : "memory");
}
__device__ __forceinline__ void mbar_arrive_cluster(uint32_t addr)
{
    asm volatile("mbarrier.arrive.release.cluster.shared::cluster.b64 _, [%0];" :: "r"(addr) : "memory");
}
__device__ __forceinline__ void mbar_wait_parity(uint32_t addr, uint32_t parity)
{
    asm volatile(
        "{\n\t"
        ".reg .pred P;\n\t"
        "WL_%=:\n\t"
        "mbarrier.try_wait.parity.acquire.cluster.shared::cta.b64 P, [%0], %1, 0x989680;\n\t"
        "@P bra.uni WD_%=;\n\t"
        "bra.uni WL_%=;\n\t"
        "WD_%=:\n\t"
        "}"
        :: "r"(addr), "r"(parity) : "memory");
}
__device__ __forceinline__ void cluster_sync_all()
{
    asm volatile("barrier.cluster.arrive.aligned;" ::: "memory");
    asm volatile("barrier.cluster.wait.aligned;" ::: "memory");
}

// =====================================================================
// Kernel 1: fused precompute GEMM (FFMA2 inner product)
//   out[r, n] = sum_k x[r,k] * W[n,k] + bias[n]
//   n <  512 : W = Wx  = tau_w[n, 0:512]   -> g_xp
//   n >= 512 : W = mem_w[n-512, :]         -> g_m
//   row r = b*T + t ; output written at [t][b][e]
// =====================================================================
__global__ void __launch_bounds__(256, 2) pre_gemm(
    const float* __restrict__ x,
    const float* __restrict__ tau_w,
    const float* __restrict__ tau_b,
    const float* __restrict__ mem_w,
    const float* __restrict__ mem_b)
{
    constexpr int Bb = 128, Bn = 128, Bk = 16;
    __shared__ float As[Bk][Bb + 4];
    __shared__ float Bs[Bk][Bn + 4];

    const int tid = threadIdx.x;
    const int m0 = blockIdx.y * Bb;
    const int n0 = blockIdx.x * Bn;

    const float* wbase;
    const float* bias;
    int rstride;
    float* outg;
    if (n0 < 512) { wbase = tau_w + (size_t)n0 * 1024; rstride = 1024; bias = tau_b + n0; outg = g_xp; }
    else          { wbase = mem_w + (size_t)(n0 - 512) * 512; rstride = 512; bias = mem_b + (n0 - 512); outg = g_m; }

    const int tm = tid >> 4;     // 0..15
    const int tn = tid & 15;     // 0..15

    unsigned long long acc2[8][4];   // 8 i-rows x 4 f32x2 pairs (8 j-cols)
#pragma unroll
    for (int i = 0; i < 8; i++)
#pragma unroll
        for (int p = 0; p < 4; p++) acc2[i][p] = 0ULL;

    for (int kk = 0; kk < 512; kk += Bk) {
#pragma unroll
        for (int u = 0; u < 2; u++) {
            int v   = tid + 256 * u;       // 0..511
            int row = v >> 2;              // 0..127
            int kc  = (v & 3) * 4;         // 0,4,8,12
            float4 a = *reinterpret_cast<const float4*>(&x[(size_t)(m0 + row) * 512 + kk + kc]);
            As[kc + 0][row] = a.x; As[kc + 1][row] = a.y; As[kc + 2][row] = a.z; As[kc + 3][row] = a.w;
            float4 b = *reinterpret_cast<const float4*>(&wbase[(size_t)row * rstride + kk + kc]);
            Bs[kc + 0][row] = b.x; Bs[kc + 1][row] = b.y; Bs[kc + 2][row] = b.z; Bs[kc + 3][row] = b.w;
        }
        __syncthreads();

#pragma unroll
        for (int k = 0; k < Bk; k++) {
            float af[8];
            *reinterpret_cast<float4*>(&af[0]) = *reinterpret_cast<const float4*>(&As[k][tm * 8]);
            *reinterpret_cast<float4*>(&af[4]) = *reinterpret_cast<const float4*>(&As[k][tm * 8 + 4]);
            ulonglong2 b01 = *reinterpret_cast<const ulonglong2*>(&Bs[k][tn * 8]);
            ulonglong2 b23 = *reinterpret_cast<const ulonglong2*>(&Bs[k][tn * 8 + 4]);
#pragma unroll
            for (int i = 0; i < 8; i++) {
                unsigned long long a2 = pack2(af[i], af[i]);
                acc2[i][0] = fma2(a2, b01.x, acc2[i][0]);
                acc2[i][1] = fma2(a2, b01.y, acc2[i][1]);
                acc2[i][2] = fma2(a2, b23.x, acc2[i][2]);
                acc2[i][3] = fma2(a2, b23.y, acc2[i][3]);
            }
        }
        __syncthreads();
    }

#pragma unroll
    for (int i = 0; i < 8; i++) {
        int r = m0 + tm * 8 + i;
        int b = r >> 10;
        int t = r & 1023;
        size_t rowoff = (size_t)t * BD + (size_t)b * DD;
#pragma unroll
        for (int p = 0; p < 4; p++) {
            float2 f = unpack2(acc2[i][p]);
            int n  = n0 + tn * 8 + 2 * p;
            outg[rowoff + ((n + 0) & 511)] = f.x + bias[tn * 8 + 2 * p + 0];
            outg[rowoff + ((n + 1) & 511)] = f.y + bias[tn * 8 + 2 * p + 1];
        }
    }
}

// =====================================================================
// Kernel 2: cluster-local scan.
// 16 clusters x 8 CTAs; each cluster owns 4 batches.
// CTA rank r owns e-slice [r*64, r*64+64) and holds Wt[e-slice, all 512 k]
// in registers (128 floats/thread). Each step:
//   - compute z[b][e] for its e-slice over full k (tau from smem, broadcast)
//   - k-split reduce in smem, sigmoid/exp/v update, spike store
//   - broadcast its 256 new tau values to all 8 CTAs' tau buffer (DSMEM)
//   - one cluster-wide mbarrier sync (8 arrivals), double-buffered tau
// =====================================================================
__global__ void __launch_bounds__(256, 1) __cluster_dims__(8, 1, 1)
scan_kernel(const float* __restrict__ tau_w,
            const float* __restrict__ thr_p,
            float* __restrict__ out)
{
    __shared__ alignas(16) float tau_s[2][4][512];   // [buf][b][k]  16KB
    __shared__ alignas(16) float red_s[4][4][64];    // [kq][b][el]   4KB
    __shared__ alignas(8)  unsigned long long mbar[1];

    const int tid = threadIdx.x;
    const uint32_t rank = ctarank();
    const int cid = blockIdx.x >> 3;       // cluster id 0..15
    const int b0  = cid * 4;               // 4 batches per cluster
    const int e0  = (int)rank * 64;        // e-slice

    const int el = tid & 63;               // e within slice (also elementwise e)
    const int kq = tid >> 6;               // k quarter 0..3 (also elementwise b)
    const int e  = e0 + el;
    const int k0 = kq * 128;

    // Wt[e, k0..k0+127] in registers, as 32 ulonglong2 (4 floats each)
    ulonglong2 wv[32];
    {
        const ulonglong2* wrow = reinterpret_cast<const ulonglong2*>(
            tau_w + (size_t)e * 1024 + 512 + k0);
#pragma unroll
        for (int i = 0; i < 32; i++) wv[i] = wrow[i];
    }

    // elementwise mapping: this thread owns pair (b = b0+kq, e = e0+el)
    const int pb = kq;
    const int pe = e;

    // init mbarrier + tau buffer 0 = 1.0
    const uint32_t mb = smem_u32(mbar);
    if (tid == 0) mbar_init(mb, 8);
    {
        float* t0 = &tau_s[0][0][0];
        for (int i = tid; i < 2048; i += 256) t0[i] = 1.0f;
    }
    __syncthreads();
    cluster_sync_all();     // all mbarriers + buffers ready cluster-wide

    // peer addresses
    uint32_t peer_mb[8], peer_tau[8];
    const uint32_t tau_base = smem_u32(&tau_s[0][0][0]);
#pragma unroll
    for (int r = 0; r < 8; r++) {
        peer_mb[r]  = mapa_rank(mb, r);
        peer_tau[r] = mapa_rank(tau_base, r);
    }

    float v = 0.0f;
    const float thr = *thr_p;

    float* out_spk = out;
    float* out_tau = out + BTD;
    float* out_v   = out + BTD + BD;

    const float* tbase = &tau_s[0][0][0];

    for (int t = 0; t < TT; t++) {
        const int cur = t & 1;
        const int nxt = cur ^ 1;

        // prefetch xp/m (latency hidden behind compute)
        const size_t goff = (size_t)t * BD + (size_t)(b0 + pb) * DD + pe;
        const float xpv = __ldcs(&g_xp[goff]);
        const float mv  = __ldcs(&g_m[goff]);

        // z partials over this thread's 128-k slice, 4 batches
        unsigned long long a0 = 0, a1 = 0, a2 = 0, a3 = 0;
        const float* tb = tbase + cur * 2048 + k0;
#pragma unroll
        for (int jq = 0; jq < 32; jq++) {
            const ulonglong2 w2 = wv[jq];
            ulonglong2 t20 = *reinterpret_cast<const ulonglong2*>(tb + 0 * 512 + jq * 4);
            ulonglong2 t21 = *reinterpret_cast<const ulonglong2*>(tb + 1 * 512 + jq * 4);
            ulonglong2 t22 = *reinterpret_cast<const ulonglong2*>(tb + 2 * 512 + jq * 4);
            ulonglong2 t23 = *reinterpret_cast<const ulonglong2*>(tb + 3 * 512 + jq * 4);
            a0 = fma2(w2.x, t20.x, a0); a0 = fma2(w2.y, t20.y, a0);
            a1 = fma2(w2.x, t21.x, a1); a1 = fma2(w2.y, t21.y, a1);
            a2 = fma2(w2.x, t22.x, a2); a2 = fma2(w2.y, t22.y, a2);
            a3 = fma2(w2.x, t23.x, a3); a3 = fma2(w2.y, t23.y, a3);
        }
        {
            float2 f;
            f = unpack2(a0); red_s[kq][0][el] = f.x + f.y;
            f = unpack2(a1); red_s[kq][1][el] = f.x + f.y;
            f = unpack2(a2); red_s[kq][2][el] = f.x + f.y;
            f = unpack2(a3); red_s[kq][3][el] = f.x + f.y;
        }
        __syncthreads();

        float z = xpv + red_s[0][pb][el] + red_s[1][pb][el]
                      + red_s[2][pb][el] + red_s[3][pb][el];

        const float ta = 1.0f / (1.0f + expf(-z));
        const float al = expf(-1.0f / (ta + 1e-6f));
        v = al * v + (1.0f - al) * mv;
        const float s = (v >= thr) ? 1.0f : 0.0f;
        __stcs(&out_spk[(size_t)(b0 + pb) * TT * DD + (size_t)t * DD + pe], s);
        v = v * (1.0f - s);

        if (t < TT - 1) {
            // broadcast new tau to all 8 CTAs' buf[nxt]
            const uint32_t toff = (uint32_t)(nxt * 2048 + pb * 512 + pe) * 4u;
#pragma unroll
            for (int r = 0; r < 8; r++) st_cluster_f32(peer_tau[r] + toff, ta);

            __syncthreads();                      // whole CTA done writing
            if (tid == 0) {
#pragma unroll
                for (int r = 0; r < 8; r++) mbar_arrive_cluster(peer_mb[r]);
            }
            mbar_wait_parity(mb, (uint32_t)(t & 1));
        } else {
            out_tau[(size_t)(b0 + pb) * DD + pe] = ta;
            out_v  [(size_t)(b0 + pb) * DD + pe] = v;
        }
    }
}

// =====================================================================
extern "C" void kernel_launch(void* const* d_in, const int* in_sizes, int n_in,
                              void* d_out, int out_size)
{
    const float* x     = (const float*)d_in[0];
    const float* tau_w = (const float*)d_in[1];
    const float* tau_b = (const float*)d_in[2];
    const float* mem_w = (const float*)d_in[3];
    const float* mem_b = (const float*)d_in[4];
    const float* thr   = (const float*)d_in[5];
    float* out = (float*)d_out;

    dim3 ggrid(8, 512);                 // N tiles x M tiles
    pre_gemm<<<ggrid, 256>>>(x, tau_w, tau_b, mem_w, mem_b);
    scan_kernel<<<128, 256>>>(tau_w, thr, out);
}

// round 4
// speedup vs baseline: 1.1220x; 1.1220x over previous
#include <cuda_runtime.h>
#include <cuda_bf16.h>
#include <cstdint>

// Problem constants
#define BB 64
#define TT 1024
#define DD 512
#define BD (BB * DD)          // 32768
#define BTD ((size_t)BB * TT * DD)

// ---------------- scratch (no allocations allowed) ----------------
__device__ float g_xp[(size_t)TT * BB * DD];   // xproj, layout [t][b][e]
__device__ float g_m [(size_t)TT * BB * DD];   // m,     layout [t][b][e]
__device__ float g_tau[2][BD];                 // ping-pong tau state [b][e]
__device__ unsigned int g_count;               // monotonic grid barrier counter

// ---------------- f32x2 packed-FMA helpers ----------------
__device__ __forceinline__ unsigned long long fma2(unsigned long long a,
                                                   unsigned long long b,
                                                   unsigned long long c)
{
    unsigned long long d;
    asm("fma.rn.f32x2 %0, %1, %2, %3;" : "=l"(d) : "l"(a), "l"(b), "l"(c));
    return d;
}
__device__ __forceinline__ unsigned long long pack2(float lo, float hi)
{
    unsigned long long r;
    asm("mov.b64 %0, {%1, %2};" : "=l"(r) : "f"(lo), "f"(hi));
    return r;
}
__device__ __forceinline__ float2 unpack2(unsigned long long v)
{
    float2 f;
    asm("mov.b64 {%0, %1}, %2;" : "=f"(f.x), "=f"(f.y) : "l"(v));
    return f;
}
__device__ __forceinline__ unsigned int ldacq(const unsigned int* p)
{
    unsigned int v;
    asm volatile("ld.acquire.gpu.u32 %0, [%1];" : "=r"(v) : "l"(p));
    return v;
}

// =====================================================================
// Kernel 0: init (per-launch reset of barrier counter + tau0 = 1)
// =====================================================================
__global__ void __launch_bounds__(512) init_kernel()
{
    int i = blockIdx.x * 512 + threadIdx.x;   // grid 64 x 512 = 32768
    g_tau[0][i] = 1.0f;
    if (i == 0) g_count = 0u;
}

// =====================================================================
// Kernel 1: fused precompute GEMM (FFMA2 inner product)
//   out[r, n] = sum_k x[r,k] * W[n,k] + bias[n]
//   n <  512 : W = Wx  = tau_w[n, 0:512]   -> g_xp
//   n >= 512 : W = mem_w[n-512, :]         -> g_m
//   row r = b*T + t ; output written at [t][b][e]
// =====================================================================
__global__ void __launch_bounds__(256, 2) pre_gemm(
    const float* __restrict__ x,
    const float* __restrict__ tau_w,
    const float* __restrict__ tau_b,
    const float* __restrict__ mem_w,
    const float* __restrict__ mem_b)
{
    constexpr int Bb = 128, Bn = 128, Bk = 16;
    __shared__ float As[Bk][Bb + 4];
    __shared__ float Bs[Bk][Bn + 4];

    const int tid = threadIdx.x;
    const int m0 = blockIdx.y * Bb;
    const int n0 = blockIdx.x * Bn;

    const float* wbase;
    const float* bias;
    int rstride;
    float* outg;
    if (n0 < 512) { wbase = tau_w + (size_t)n0 * 1024; rstride = 1024; bias = tau_b + n0; outg = g_xp; }
    else          { wbase = mem_w + (size_t)(n0 - 512) * 512; rstride = 512; bias = mem_b + (n0 - 512); outg = g_m; }

    const int tm = tid >> 4;     // 0..15
    const int tn = tid & 15;     // 0..15

    unsigned long long acc2[8][4];   // 8 i-rows x 4 f32x2 pairs (8 j-cols)
#pragma unroll
    for (int i = 0; i < 8; i++)
#pragma unroll
        for (int p = 0; p < 4; p++) acc2[i][p] = 0ULL;

    for (int kk = 0; kk < 512; kk += Bk) {
#pragma unroll
        for (int u = 0; u < 2; u++) {
            int v   = tid + 256 * u;       // 0..511
            int row = v >> 2;              // 0..127
            int kc  = (v & 3) * 4;         // 0,4,8,12
            float4 a = *reinterpret_cast<const float4*>(&x[(size_t)(m0 + row) * 512 + kk + kc]);
            As[kc + 0][row] = a.x; As[kc + 1][row] = a.y; As[kc + 2][row] = a.z; As[kc + 3][row] = a.w;
            float4 b = *reinterpret_cast<const float4*>(&wbase[(size_t)row * rstride + kk + kc]);
            Bs[kc + 0][row] = b.x; Bs[kc + 1][row] = b.y; Bs[kc + 2][row] = b.z; Bs[kc + 3][row] = b.w;
        }
        __syncthreads();

#pragma unroll
        for (int k = 0; k < Bk; k++) {
            float af[8];
            *reinterpret_cast<float4*>(&af[0]) = *reinterpret_cast<const float4*>(&As[k][tm * 8]);
            *reinterpret_cast<float4*>(&af[4]) = *reinterpret_cast<const float4*>(&As[k][tm * 8 + 4]);
            ulonglong2 b01 = *reinterpret_cast<const ulonglong2*>(&Bs[k][tn * 8]);
            ulonglong2 b23 = *reinterpret_cast<const ulonglong2*>(&Bs[k][tn * 8 + 4]);
#pragma unroll
            for (int i = 0; i < 8; i++) {
                unsigned long long a2 = pack2(af[i], af[i]);
                acc2[i][0] = fma2(a2, b01.x, acc2[i][0]);
                acc2[i][1] = fma2(a2, b01.y, acc2[i][1]);
                acc2[i][2] = fma2(a2, b23.x, acc2[i][2]);
                acc2[i][3] = fma2(a2, b23.y, acc2[i][3]);
            }
        }
        __syncthreads();
    }

#pragma unroll
    for (int i = 0; i < 8; i++) {
        int r = m0 + tm * 8 + i;
        int b = r >> 10;
        int t = r & 1023;
        size_t rowoff = (size_t)t * BD + (size_t)b * DD;
#pragma unroll
        for (int p = 0; p < 4; p++) {
            float2 f = unpack2(acc2[i][p]);
            int n  = n0 + tn * 8 + 2 * p;
            outg[rowoff + ((n + 0) & 511)] = f.x + bias[tn * 8 + 2 * p + 0];
            outg[rowoff + ((n + 1) & 511)] = f.y + bias[tn * 8 + 2 * p + 1];
        }
    }
}

// =====================================================================
// Kernel 2: persistent scan, register-blocked (4e x 16k per thread).
// grid = 128 CTAs = 16 e-tiles(32e) x 8 b-tiles(8b), 256 threads.
// Thread (et=tid>>5, ks=tid&31): holds Wt[e0+et*4 .. +4, ks*16 .. +16)
// in registers (64 floats). Computes partials for 8 batches.
// 32-way k-split reduced via stride-33 padded smem (conflict-free).
// Grid barrier: monotonic counter, 1 atomicAdd per CTA, warp-coalesced
// acquire poll by all threads (no releaser relay).
// =====================================================================
__device__ __forceinline__ void gbar(unsigned int target)
{
    __syncthreads();                              // all tau stores issued
    if (threadIdx.x == 0) {
        __threadfence();                          // publish CTA's writes (cumulative via bar)
        atomicAdd(&g_count, 1u);
    }
    while ((int)(ldacq(&g_count) - target) < 0) {}
}

__global__ void __launch_bounds__(256, 1) scan_kernel(
    const float* __restrict__ tau_w,
    const float* __restrict__ thr_p,
    float* __restrict__ out)
{
    __shared__ alignas(16) float tau_s[2][8][512];   // 32 KB, double-buffered
    __shared__ float red_s[256 * 33];                // ~34 KB, stride-33 padded

    const int tid = threadIdx.x;
    const int eb = blockIdx.x & 15;        // e-tile
    const int bb = blockIdx.x >> 4;        // b-tile
    const int e0 = eb * 32;
    const int b0 = bb * 8;

    const int ks = tid & 31;               // k-slice (16 k each)
    const int et = tid >> 5;               // e-group (4 e each)

    // Wt[4e, 16k] in registers as f32x2
    unsigned long long w2[4][8];
#pragma unroll
    for (int ei = 0; ei < 4; ei++) {
        const ulonglong2* wr = reinterpret_cast<const ulonglong2*>(
            tau_w + (size_t)(e0 + et * 4 + ei) * 1024 + 512 + ks * 16);
#pragma unroll
        for (int j2 = 0; j2 < 4; j2++) {
            ulonglong2 u = wr[j2];
            w2[ei][2 * j2 + 0] = u.x;
            w2[ei][2 * j2 + 1] = u.y;
        }
    }

    // elementwise mapping: thread owns (b = b0 + tid>>5, e = e0 + tid&31)
    const int pb = b0 + (tid >> 5);
    const int pe = e0 + (tid & 31);

    float v = 0.0f;
    const float thr = *thr_p;

    float* out_spk = out;
    float* out_tau = out + BTD;
    float* out_v   = out + BTD + BD;

    // prime xp/m prefetch for t=0
    size_t goff = (size_t)pb * DD + pe;
    float xpv = __ldcs(&g_xp[goff]);
    float mv  = __ldcs(&g_m[goff]);

    for (int t = 0; t < TT; t++) {
        const int cur = t & 1;
        const int nxt = cur ^ 1;

        // stage tau for 8 batches: 16KB via L2-coherent loads
        {
            const float4* src = reinterpret_cast<const float4*>(&g_tau[cur][b0 * DD]);
            float4* dst = reinterpret_cast<float4*>(&tau_s[cur][0][0]);
#pragma unroll
            for (int i = 0; i < 4; i++) dst[tid + 256 * i] = __ldcg(src + tid + 256 * i);
        }

        // prefetch next step's xp/m (hidden behind compute)
        float xpn = 0.0f, mvn = 0.0f;
        if (t + 1 < TT) {
            size_t goff2 = (size_t)(t + 1) * BD + (size_t)pb * DD + pe;
            xpn = __ldcs(&g_xp[goff2]);
            mvn = __ldcs(&g_m[goff2]);
        }
        __syncthreads();

        // register-blocked partial dots: 4 e x 8 b x 16 k per thread
        unsigned long long acc[4][8];
#pragma unroll
        for (int ei = 0; ei < 4; ei++)
#pragma unroll
            for (int bl = 0; bl < 8; bl++) acc[ei][bl] = 0ULL;

        const float* tb = &tau_s[cur][0][ks * 16];
#pragma unroll
        for (int bl = 0; bl < 8; bl++) {
            const ulonglong2* tp = reinterpret_cast<const ulonglong2*>(tb + bl * 512);
            unsigned long long t8[8];
#pragma unroll
            for (int j2 = 0; j2 < 4; j2++) {
                ulonglong2 u = tp[j2];
                t8[2 * j2 + 0] = u.x;
                t8[2 * j2 + 1] = u.y;
            }
#pragma unroll
            for (int ei = 0; ei < 4; ei++)
#pragma unroll
                for (int j = 0; j < 8; j++)
                    acc[ei][bl] = fma2(w2[ei][j], t8[j], acc[ei][bl]);
        }

        // store partials: red_s[(bl*32 + et*4+ei)*33 + ks]  (conflict-free)
#pragma unroll
        for (int ei = 0; ei < 4; ei++)
#pragma unroll
            for (int bl = 0; bl < 8; bl++) {
                float2 f = unpack2(acc[ei][bl]);
                red_s[(bl * 32 + et * 4 + ei) * 33 + ks] = f.x + f.y;
            }
        __syncthreads();

        // reduce 32 partials: output index == tid
        float z = xpv;
        {
            const float* rp = &red_s[tid * 33];
#pragma unroll
            for (int i = 0; i < 32; i++) z += rp[i];
        }

        // tau' = sigmoid(z) ; alpha = exp(-1/(tau'+1e-6))
        const float ta = 1.0f / (1.0f + expf(-z));
        const float al = expf(-1.0f / (ta + 1e-6f));
        v = al * v + (1.0f - al) * mv;
        const float s = (v >= thr) ? 1.0f : 0.0f;
        __stcs(&out_spk[(size_t)pb * TT * DD + (size_t)t * DD + pe], s);
        v = v * (1.0f - s);

        if (t < TT - 1) {
            __stcg(&g_tau[nxt][pb * DD + pe], ta);
        } else {
            out_tau[pb * DD + pe] = ta;
            out_v  [pb * DD + pe] = v;
        }

        gbar(128u * (unsigned)(t + 1));
        xpv = xpn;
        mv  = mvn;
    }
}

// =====================================================================
extern "C" void kernel_launch(void* const* d_in, const int* in_sizes, int n_in,
                              void* d_out, int out_size)
{
    const float* x     = (const float*)d_in[0];
    const float* tau_w = (const float*)d_in[1];
    const float* tau_b = (const float*)d_in[2];
    const float* mem_w = (const float*)d_in[3];
    const float* mem_b = (const float*)d_in[4];
    const float* thr   = (const float*)d_in[5];
    float* out = (float*)d_out;

    init_kernel<<<64, 512>>>();
    dim3 ggrid(8, 512);                 // N tiles x M tiles
    pre_gemm<<<ggrid, 256>>>(x, tau_w, tau_b, mem_w, mem_b);
    scan_kernel<<<128, 256>>>(tau_w, thr, out);
}

// round 5
// speedup vs baseline: 1.2389x; 1.1042x over previous
#include <cuda_runtime.h>
#include <cuda_bf16.h>
#include <cstdint>

// Problem constants
#define BB 64
#define TT 1024
#define DD 512
#define BD (BB * DD)          // 32768
#define BTD ((size_t)BB * TT * DD)

// ---------------- scratch (no allocations allowed) ----------------
__device__ float g_xp[(size_t)TT * BB * DD];   // xproj, layout [t][b][e]
__device__ float g_m [(size_t)TT * BB * DD];   // m,     layout [t][b][e]
__device__ float g_tau[2][BD];                 // ping-pong tau state [b][e]
__device__ unsigned int g_count;               // monotonic grid barrier counter

// ---------------- f32x2 packed-FMA helpers ----------------
__device__ __forceinline__ unsigned long long fma2(unsigned long long a,
                                                   unsigned long long b,
                                                   unsigned long long c)
{
    unsigned long long d;
    asm("fma.rn.f32x2 %0, %1, %2, %3;" : "=l"(d) : "l"(a), "l"(b), "l"(c));
    return d;
}
__device__ __forceinline__ unsigned long long pack2(float lo, float hi)
{
    unsigned long long r;
    asm("mov.b64 %0, {%1, %2};" : "=l"(r) : "f"(lo), "f"(hi));
    return r;
}
__device__ __forceinline__ float2 unpack2(unsigned long long v)
{
    float2 f;
    asm("mov.b64 {%0, %1}, %2;" : "=f"(f.x), "=f"(f.y) : "l"(v));
    return f;
}
__device__ __forceinline__ unsigned int ldacq(const unsigned int* p)
{
    unsigned int v;
    asm volatile("ld.acquire.gpu.u32 %0, [%1];" : "=r"(v) : "l"(p));
    return v;
}

// =====================================================================
// Kernel 0: init (per-launch reset of barrier counter + tau0 = 1)
// =====================================================================
__global__ void __launch_bounds__(512) init_kernel()
{
    int i = blockIdx.x * 512 + threadIdx.x;   // grid 64 x 512 = 32768
    g_tau[0][i] = 1.0f;
    if (i == 0) g_count = 0u;
}

// =====================================================================
// Kernel 1: fused precompute GEMM (FFMA2 inner product)
//   out[r, n] = sum_k x[r,k] * W[n,k] + bias[n]
//   n <  512 : W = Wx  = tau_w[n, 0:512]   -> g_xp
//   n >= 512 : W = mem_w[n-512, :]         -> g_m
//   row r = b*T + t ; output written at [t][b][e]
// =====================================================================
__global__ void __launch_bounds__(256, 2) pre_gemm(
    const float* __restrict__ x,
    const float* __restrict__ tau_w,
    const float* __restrict__ tau_b,
    const float* __restrict__ mem_w,
    const float* __restrict__ mem_b)
{
    constexpr int Bb = 128, Bn = 128, Bk = 16;
    __shared__ float As[Bk][Bb + 4];
    __shared__ float Bs[Bk][Bn + 4];

    const int tid = threadIdx.x;
    const int m0 = blockIdx.y * Bb;
    const int n0 = blockIdx.x * Bn;

    const float* wbase;
    const float* bias;
    int rstride;
    float* outg;
    if (n0 < 512) { wbase = tau_w + (size_t)n0 * 1024; rstride = 1024; bias = tau_b + n0; outg = g_xp; }
    else          { wbase = mem_w + (size_t)(n0 - 512) * 512; rstride = 512; bias = mem_b + (n0 - 512); outg = g_m; }

    const int tm = tid >> 4;     // 0..15
    const int tn = tid & 15;     // 0..15

    unsigned long long acc2[8][4];   // 8 i-rows x 4 f32x2 pairs (8 j-cols)
#pragma unroll
    for (int i = 0; i < 8; i++)
#pragma unroll
        for (int p = 0; p < 4; p++) acc2[i][p] = 0ULL;

    for (int kk = 0; kk < 512; kk += Bk) {
#pragma unroll
        for (int u = 0; u < 2; u++) {
            int v   = tid + 256 * u;       // 0..511
            int row = v >> 2;              // 0..127
            int kc  = (v & 3) * 4;         // 0,4,8,12
            float4 a = *reinterpret_cast<const float4*>(&x[(size_t)(m0 + row) * 512 + kk + kc]);
            As[kc + 0][row] = a.x; As[kc + 1][row] = a.y; As[kc + 2][row] = a.z; As[kc + 3][row] = a.w;
            float4 b = *reinterpret_cast<const float4*>(&wbase[(size_t)row * rstride + kk + kc]);
            Bs[kc + 0][row] = b.x; Bs[kc + 1][row] = b.y; Bs[kc + 2][row] = b.z; Bs[kc + 3][row] = b.w;
        }
        __syncthreads();

#pragma unroll
        for (int k = 0; k < Bk; k++) {
            float af[8];
            *reinterpret_cast<float4*>(&af[0]) = *reinterpret_cast<const float4*>(&As[k][tm * 8]);
            *reinterpret_cast<float4*>(&af[4]) = *reinterpret_cast<const float4*>(&As[k][tm * 8 + 4]);
            ulonglong2 b01 = *reinterpret_cast<const ulonglong2*>(&Bs[k][tn * 8]);
            ulonglong2 b23 = *reinterpret_cast<const ulonglong2*>(&Bs[k][tn * 8 + 4]);
#pragma unroll
            for (int i = 0; i < 8; i++) {
                unsigned long long a2 = pack2(af[i], af[i]);
                acc2[i][0] = fma2(a2, b01.x, acc2[i][0]);
                acc2[i][1] = fma2(a2, b01.y, acc2[i][1]);
                acc2[i][2] = fma2(a2, b23.x, acc2[i][2]);
                acc2[i][3] = fma2(a2, b23.y, acc2[i][3]);
            }
        }
        __syncthreads();
    }

#pragma unroll
    for (int i = 0; i < 8; i++) {
        int r = m0 + tm * 8 + i;
        int b = r >> 10;
        int t = r & 1023;
        size_t rowoff = (size_t)t * BD + (size_t)b * DD;
#pragma unroll
        for (int p = 0; p < 4; p++) {
            float2 f = unpack2(acc2[i][p]);
            int n  = n0 + tn * 8 + 2 * p;
            outg[rowoff + ((n + 0) & 511)] = f.x + bias[tn * 8 + 2 * p + 0];
            outg[rowoff + ((n + 1) & 511)] = f.y + bias[tn * 8 + 2 * p + 1];
        }
    }
}

// =====================================================================
// Kernel 2: persistent scan, register-blocked 4e x 16k per thread,
// accumulators flushed per-batch (8 live regs, no spills).
// grid = 128 CTAs = 16 e-tiles(32e) x 8 b-tiles(8b), 256 threads.
// Barrier: monotonic counter, thread-0 arrive + poll, syncthreads fan-out.
// =====================================================================
__device__ __forceinline__ void gbar(unsigned int target)
{
    __syncthreads();                              // all tau stores issued
    if (threadIdx.x == 0) {
        __threadfence();                          // publish CTA writes (cumulative via bar)
        atomicAdd(&g_count, 1u);
        while ((int)(ldacq(&g_count) - target) < 0) {}
    }
    __syncthreads();
}

__global__ void __launch_bounds__(256, 1) scan_kernel(
    const float* __restrict__ tau_w,
    const float* __restrict__ thr_p,
    float* __restrict__ out)
{
    __shared__ alignas(16) float tau_s[2][8][512];   // 32 KB, double-buffered
    __shared__ float red_s[8][32][33];               // ~34 KB, padded

    const int tid = threadIdx.x;
    const int eb = blockIdx.x & 15;        // e-tile
    const int bb = blockIdx.x >> 4;        // b-tile
    const int e0 = eb * 32;
    const int b0 = bb * 8;

    const int ks = tid & 31;               // k-slice (16 k each)
    const int et = tid >> 5;               // e-group (4 e each) == warp id

    // Wt[4e, 16k] in registers as f32x2 (64 regs)
    unsigned long long w2[4][8];
#pragma unroll
    for (int ei = 0; ei < 4; ei++) {
        const ulonglong2* wr = reinterpret_cast<const ulonglong2*>(
            tau_w + (size_t)(e0 + et * 4 + ei) * 1024 + 512 + ks * 16);
#pragma unroll
        for (int j2 = 0; j2 < 4; j2++) {
            ulonglong2 u = wr[j2];
            w2[ei][2 * j2 + 0] = u.x;
            w2[ei][2 * j2 + 1] = u.y;
        }
    }

    // elementwise mapping: thread owns (b = b0 + tid>>5, e = e0 + tid&31)
    const int pbl = tid >> 5;              // batch within tile
    const int pel = tid & 31;              // e within tile
    const int pb = b0 + pbl;
    const int pe = e0 + pel;

    float v = 0.0f;
    const float thr = *thr_p;

    float* out_spk = out;
    float* out_tau = out + BTD;
    float* out_v   = out + BTD + BD;

    // prime xp/m prefetch for t=0
    float xpv = __ldcs(&g_xp[(size_t)pb * DD + pe]);
    float mv  = __ldcs(&g_m [(size_t)pb * DD + pe]);

    for (int t = 0; t < TT; t++) {
        const int cur = t & 1;
        const int nxt = cur ^ 1;

        // stage tau for 8 batches: 16KB via L2-coherent loads
        {
            const float4* src = reinterpret_cast<const float4*>(&g_tau[cur][b0 * DD]);
            float4* dst = reinterpret_cast<float4*>(&tau_s[cur][0][0]);
#pragma unroll
            for (int i = 0; i < 4; i++) dst[tid + 256 * i] = __ldcg(src + tid + 256 * i);
        }

        // prefetch next step's xp/m (hidden behind compute)
        float xpn = 0.0f, mvn = 0.0f;
        if (t + 1 < TT) {
            size_t goff2 = (size_t)(t + 1) * BD + (size_t)pb * DD + pe;
            xpn = __ldcs(&g_xp[goff2]);
            mvn = __ldcs(&g_m[goff2]);
        }
        __syncthreads();

        // per-batch: load 16 tau values, 32 FFMA2, flush 4 partials
#pragma unroll
        for (int bl = 0; bl < 8; bl++) {
            const ulonglong2* tp = reinterpret_cast<const ulonglong2*>(
                &tau_s[cur][bl][ks * 16]);
            unsigned long long t8[8];
#pragma unroll
            for (int j2 = 0; j2 < 4; j2++) {
                ulonglong2 u = tp[j2];
                t8[2 * j2 + 0] = u.x;
                t8[2 * j2 + 1] = u.y;
            }
#pragma unroll
            for (int ei = 0; ei < 4; ei++) {
                unsigned long long a = 0ULL;
#pragma unroll
                for (int j = 0; j < 8; j++) a = fma2(w2[ei][j], t8[j], a);
                float2 f = unpack2(a);
                red_s[bl][et * 4 + ei][ks] = f.x + f.y;
            }
        }
        __syncthreads();

        // reduce 32 k-partials for this thread's (pbl, pel)
        float z = xpv;
        {
            const float* rp = &red_s[pbl][pel][0];
#pragma unroll
            for (int i = 0; i < 32; i++) z += rp[i];
        }

        // tau' = sigmoid(z) ; alpha = exp(-1/(tau'+1e-6))
        const float ta = 1.0f / (1.0f + expf(-z));
        const float al = expf(-1.0f / (ta + 1e-6f));
        v = al * v + (1.0f - al) * mv;
        const float s = (v >= thr) ? 1.0f : 0.0f;
        __stcs(&out_spk[(size_t)pb * TT * DD + (size_t)t * DD + pe], s);
        v = v * (1.0f - s);

        if (t < TT - 1) {
            __stcg(&g_tau[nxt][pb * DD + pe], ta);
        } else {
            out_tau[pb * DD + pe] = ta;
            out_v  [pb * DD + pe] = v;
        }

        gbar(128u * (unsigned)(t + 1));
        xpv = xpn;
        mv  = mvn;
    }
}

// =====================================================================
extern "C" void kernel_launch(void* const* d_in, const int* in_sizes, int n_in,
                              void* d_out, int out_size)
{
    const float* x     = (const float*)d_in[0];
    const float* tau_w = (const float*)d_in[1];
    const float* tau_b = (const float*)d_in[2];
    const float* mem_w = (const float*)d_in[3];
    const float* mem_b = (const float*)d_in[4];
    const float* thr   = (const float*)d_in[5];
    float* out = (float*)d_out;

    init_kernel<<<64, 512>>>();
    dim3 ggrid(8, 512);                 // N tiles x M tiles
    pre_gemm<<<ggrid, 256>>>(x, tau_w, tau_b, mem_w, mem_b);
    scan_kernel<<<128, 256>>>(tau_w, thr, out);
}

// round 6
// speedup vs baseline: 1.7613x; 1.4216x over previous
#include <cuda_runtime.h>
#include <cuda_bf16.h>
#include <cstdint>

// Problem constants
#define BB 64
#define TT 1024
#define DD 512
#define BD (BB * DD)          // 32768
#define BTD ((size_t)BB * TT * DD)

// ---------------- scratch (no allocations allowed) ----------------
__device__ float g_xp[(size_t)TT * BB * DD];   // xproj, layout [t][b][e]
__device__ float g_m [(size_t)TT * BB * DD];   // m,     layout [t][b][e]
__device__ float g_tau[2][BD];                 // ping-pong tau state [b][e]
__device__ unsigned int g_cnt[8 * 32];         // per-b-group barrier counters (128B apart)

// ---------------- f32x2 packed-FMA helpers ----------------
__device__ __forceinline__ unsigned long long fma2(unsigned long long a,
                                                   unsigned long long b,
                                                   unsigned long long c)
{
    unsigned long long d;
    asm("fma.rn.f32x2 %0, %1, %2, %3;" : "=l"(d) : "l"(a), "l"(b), "l"(c));
    return d;
}
__device__ __forceinline__ unsigned long long pack2(float lo, float hi)
{
    unsigned long long r;
    asm("mov.b64 %0, {%1, %2};" : "=l"(r) : "f"(lo), "f"(hi));
    return r;
}
__device__ __forceinline__ float2 unpack2(unsigned long long v)
{
    float2 f;
    asm("mov.b64 {%0, %1}, %2;" : "=f"(f.x), "=f"(f.y) : "l"(v));
    return f;
}
__device__ __forceinline__ unsigned int ldacq(const unsigned int* p)
{
    unsigned int v;
    asm volatile("ld.acquire.gpu.u32 %0, [%1];" : "=r"(v) : "l"(p));
    return v;
}

// =====================================================================
// Kernel 0: init (per-launch reset of group barrier counters)
// =====================================================================
__global__ void __launch_bounds__(256) init_kernel()
{
    if (threadIdx.x < 8 * 32) g_cnt[threadIdx.x] = 0u;
}

// =====================================================================
// Kernel 1: fused precompute GEMM (FFMA2 inner product)
//   out[r, n] = sum_k x[r,k] * W[n,k] + bias[n]
//   n <  512 : W = Wx  = tau_w[n, 0:512]   -> g_xp
//   n >= 512 : W = mem_w[n-512, :]         -> g_m
//   row r = b*T + t ; output written at [t][b][e]
// =====================================================================
__global__ void __launch_bounds__(256, 2) pre_gemm(
    const float* __restrict__ x,
    const float* __restrict__ tau_w,
    const float* __restrict__ tau_b,
    const float* __restrict__ mem_w,
    const float* __restrict__ mem_b)
{
    constexpr int Bb = 128, Bn = 128, Bk = 16;
    __shared__ float As[Bk][Bb + 4];
    __shared__ float Bs[Bk][Bn + 4];

    const int tid = threadIdx.x;
    const int m0 = blockIdx.y * Bb;
    const int n0 = blockIdx.x * Bn;

    const float* wbase;
    const float* bias;
    int rstride;
    float* outg;
    if (n0 < 512) { wbase = tau_w + (size_t)n0 * 1024; rstride = 1024; bias = tau_b + n0; outg = g_xp; }
    else          { wbase = mem_w + (size_t)(n0 - 512) * 512; rstride = 512; bias = mem_b + (n0 - 512); outg = g_m; }

    const int tm = tid >> 4;     // 0..15
    const int tn = tid & 15;     // 0..15

    unsigned long long acc2[8][4];   // 8 i-rows x 4 f32x2 pairs (8 j-cols)
#pragma unroll
    for (int i = 0; i < 8; i++)
#pragma unroll
        for (int p = 0; p < 4; p++) acc2[i][p] = 0ULL;

    for (int kk = 0; kk < 512; kk += Bk) {
#pragma unroll
        for (int u = 0; u < 2; u++) {
            int v   = tid + 256 * u;       // 0..511
            int row = v >> 2;              // 0..127
            int kc  = (v & 3) * 4;         // 0,4,8,12
            float4 a = *reinterpret_cast<const float4*>(&x[(size_t)(m0 + row) * 512 + kk + kc]);
            As[kc + 0][row] = a.x; As[kc + 1][row] = a.y; As[kc + 2][row] = a.z; As[kc + 3][row] = a.w;
            float4 b = *reinterpret_cast<const float4*>(&wbase[(size_t)row * rstride + kk + kc]);
            Bs[kc + 0][row] = b.x; Bs[kc + 1][row] = b.y; Bs[kc + 2][row] = b.z; Bs[kc + 3][row] = b.w;
        }
        __syncthreads();

#pragma unroll
        for (int k = 0; k < Bk; k++) {
            float af[8];
            *reinterpret_cast<float4*>(&af[0]) = *reinterpret_cast<const float4*>(&As[k][tm * 8]);
            *reinterpret_cast<float4*>(&af[4]) = *reinterpret_cast<const float4*>(&As[k][tm * 8 + 4]);
            ulonglong2 b01 = *reinterpret_cast<const ulonglong2*>(&Bs[k][tn * 8]);
            ulonglong2 b23 = *reinterpret_cast<const ulonglong2*>(&Bs[k][tn * 8 + 4]);
#pragma unroll
            for (int i = 0; i < 8; i++) {
                unsigned long long a2 = pack2(af[i], af[i]);
                acc2[i][0] = fma2(a2, b01.x, acc2[i][0]);
                acc2[i][1] = fma2(a2, b01.y, acc2[i][1]);
                acc2[i][2] = fma2(a2, b23.x, acc2[i][2]);
                acc2[i][3] = fma2(a2, b23.y, acc2[i][3]);
            }
        }
        __syncthreads();
    }

#pragma unroll
    for (int i = 0; i < 8; i++) {
        int r = m0 + tm * 8 + i;
        int b = r >> 10;
        int t = r & 1023;
        size_t rowoff = (size_t)t * BD + (size_t)b * DD;
#pragma unroll
        for (int p = 0; p < 4; p++) {
            float2 f = unpack2(acc2[i][p]);
            int n  = n0 + tn * 8 + 2 * p;
            outg[rowoff + ((n + 0) & 511)] = f.x + bias[tn * 8 + 2 * p + 0];
            outg[rowoff + ((n + 1) & 511)] = f.y + bias[tn * 8 + 2 * p + 1];
        }
    }
}

// =====================================================================
// Kernel 2: persistent scan with PER-B-GROUP sync.
// 128 CTAs = 16 e-tiles(32e) x 8 b-groups(8b). The 16 CTAs sharing a
// b-group exchange tau through L2 (ping-pong) and sync on a private
// monotonic counter. Groups are fully independent (pipelined).
// Compute mapping = R2 (broadcast LDS): thread (kq=tid>>5, el=tid&31)
// holds Wt[e0+el, kq*64..+64) in registers, partials for 8 batches.
// =====================================================================
__global__ void __launch_bounds__(256, 1) scan_kernel(
    const float* __restrict__ tau_w,
    const float* __restrict__ thr_p,
    float* __restrict__ out)
{
    __shared__ alignas(16) float tau_s[8 * 512];   // tau_t for 8 batches (16 KB)
    __shared__ float red_s[8 * 8 * 32];            // [kq][bl][el] partials (8 KB)

    const int tid = threadIdx.x;
    const int eb = blockIdx.x & 15;        // e-tile
    const int bb = blockIdx.x >> 4;        // b-group
    const int e0 = eb * 32;
    const int b0 = bb * 8;

    // compute-phase mapping
    const int kq = tid >> 5;               // 0..7  (k slice of 64)
    const int el = tid & 31;               // 0..31 (e within tile)
    const int e  = e0 + el;
    const int k0 = kq * 64;

    // Wt[e, k0..k0+63] in registers as f32x2 (constant over steps)
    ulonglong2 wv2[16];
    {
        const ulonglong2* wrow = reinterpret_cast<const ulonglong2*>(
            tau_w + (size_t)e * 1024 + 512 + k0);
#pragma unroll
        for (int i = 0; i < 16; i++) wv2[i] = wrow[i];
    }

    // elementwise mapping: thread owns (pb, pe)
    const int pbl = tid >> 5;
    const int pel = tid & 31;
    const int pb = b0 + pbl;
    const int pe = e0 + pel;

    float v = 0.0f;
    const float thr = *thr_p;
    unsigned int* const cnt = &g_cnt[bb * 32];

    float* out_spk = out;
    float* out_tau = out + BTD;
    float* out_v   = out + BTD + BD;

    // tau_0 = 1 directly in smem (no global round-trip)
    for (int i = tid; i < 4096; i += 256) tau_s[i] = 1.0f;
    // xp/m for t=0
    float xpv = __ldcs(&g_xp[(size_t)pb * DD + pe]);
    float mv  = __ldcs(&g_m [(size_t)pb * DD + pe]);
    __syncthreads();

    for (int t = 0; t < TT; t++) {
        // ---- compute partial dots from tau_s (broadcast LDS) ----
        unsigned long long acc2[8];
#pragma unroll
        for (int bl = 0; bl < 8; bl++) acc2[bl] = 0ULL;
#pragma unroll
        for (int jq = 0; jq < 16; jq++) {
            const ulonglong2 w2 = wv2[jq];
#pragma unroll
            for (int bl = 0; bl < 8; bl++) {
                const ulonglong2 t2 = *reinterpret_cast<const ulonglong2*>(
                    &tau_s[bl * 512 + k0 + jq * 4]);
                acc2[bl] = fma2(w2.x, t2.x, acc2[bl]);
                acc2[bl] = fma2(w2.y, t2.y, acc2[bl]);
            }
        }
#pragma unroll
        for (int bl = 0; bl < 8; bl++) {
            float2 f = unpack2(acc2[bl]);
            red_s[kq * 256 + bl * 32 + el] = f.x + f.y;
        }
        __syncthreads();

        // ---- reduce + new tau ----
        float z = xpv;
#pragma unroll
        for (int q = 0; q < 8; q++) z += red_s[q * 256 + pbl * 32 + pel];
        const float ta = 1.0f / (1.0f + expf(-z));

        if (t < TT - 1) {
            // publish new tau FIRST (group critical path), then overlap rest
            __stcg(&g_tau[(t + 1) & 1][pb * DD + pe], ta);
            __syncthreads();                       // all stores issued
            if (tid == 0) {
                __threadfence();
                atomicAdd(cnt, 1u);                // arrive
            }
        }

        // ---- elementwise (overlaps tau propagation) ----
        const float al = expf(-1.0f / (ta + 1e-6f));
        v = al * v + (1.0f - al) * mv;
        const float s = (v >= thr) ? 1.0f : 0.0f;
        __stcs(&out_spk[(size_t)pb * TT * DD + (size_t)t * DD + pe], s);
        v = v * (1.0f - s);

        if (t == TT - 1) {
            out_tau[pb * DD + pe] = ta;
            out_v  [pb * DD + pe] = v;
            break;
        }

        // prefetch next xp/m
        {
            size_t goff = (size_t)(t + 1) * BD + (size_t)pb * DD + pe;
            xpv = __ldcs(&g_xp[goff]);
            mv  = __ldcs(&g_m[goff]);
        }

        // ---- wait for the 16 CTAs of this b-group ----
        if (tid == 0) {
            const unsigned int target = 16u * (unsigned)(t + 1);
            while ((int)(ldacq(cnt) - target) < 0) {}
        }
        __syncthreads();

        // ---- stage tau_{t+1} for our 8 batches (16 KB from L2) ----
        {
            const float4* src = reinterpret_cast<const float4*>(
                &g_tau[(t + 1) & 1][b0 * DD]);
            float4* dst = reinterpret_cast<float4*>(tau_s);
#pragma unroll
            for (int i = 0; i < 4; i++) dst[tid + 256 * i] = __ldcg(src + tid + 256 * i);
        }
        __syncthreads();
    }
}

// =====================================================================
extern "C" void kernel_launch(void* const* d_in, const int* in_sizes, int n_in,
                              void* d_out, int out_size)
{
    const float* x     = (const float*)d_in[0];
    const float* tau_w = (const float*)d_in[1];
    const float* tau_b = (const float*)d_in[2];
    const float* mem_w = (const float*)d_in[3];
    const float* mem_b = (const float*)d_in[4];
    const float* thr   = (const float*)d_in[5];
    float* out = (float*)d_out;

    init_kernel<<<1, 256>>>();
    dim3 ggrid(8, 512);                 // N tiles x M tiles
    pre_gemm<<<ggrid, 256>>>(x, tau_w, tau_b, mem_w, mem_b);
    scan_kernel<<<128, 256>>>(tau_w, thr, out);
}

// round 7
// speedup vs baseline: 1.7804x; 1.0109x over previous
#include <cuda_runtime.h>
#include <cuda_bf16.h>
#include <cstdint>

// Problem constants
#define BB 64
#define TT 1024
#define DD 512
#define BD (BB * DD)          // 32768
#define BTD ((size_t)BB * TT * DD)

// ---------------- scratch (no allocations allowed) ----------------
__device__ float g_xp[(size_t)TT * BB * DD];   // xproj, layout [t][b][e]
__device__ float g_m [(size_t)TT * BB * DD];   // m,     layout [t][b][e]
__device__ float g_tau[2][BD];                 // ping-pong tau state [b][e]
__device__ unsigned int g_cnt[8 * 32];         // per-b-group barrier counters (128B apart)

// ---------------- f32x2 packed-FMA helpers ----------------
__device__ __forceinline__ unsigned long long fma2(unsigned long long a,
                                                   unsigned long long b,
                                                   unsigned long long c)
{
    unsigned long long d;
    asm("fma.rn.f32x2 %0, %1, %2, %3;" : "=l"(d) : "l"(a), "l"(b), "l"(c));
    return d;
}
__device__ __forceinline__ unsigned long long pack2(float lo, float hi)
{
    unsigned long long r;
    asm("mov.b64 %0, {%1, %2};" : "=l"(r) : "f"(lo), "f"(hi));
    return r;
}
__device__ __forceinline__ float2 unpack2(unsigned long long v)
{
    float2 f;
    asm("mov.b64 {%0, %1}, %2;" : "=f"(f.x), "=f"(f.y) : "l"(v));
    return f;
}
__device__ __forceinline__ unsigned int ldacq(const unsigned int* p)
{
    unsigned int v;
    asm volatile("ld.acquire.gpu.u32 %0, [%1];" : "=r"(v) : "l"(p));
    return v;
}

// =====================================================================
// Kernel 0: init (per-launch reset of group barrier counters)
// =====================================================================
__global__ void __launch_bounds__(256) init_kernel()
{
    if (threadIdx.x < 8 * 32) g_cnt[threadIdx.x] = 0u;
}

// =====================================================================
// Kernel 1: fused precompute GEMM, double-buffered smem (1 sync/iter)
//   out[r, n] = sum_k x[r,k] * W[n,k] + bias[n]
//   n <  512 : W = Wx  = tau_w[n, 0:512]   -> g_xp
//   n >= 512 : W = mem_w[n-512, :]         -> g_m
//   row r = b*T + t ; output written at [t][b][e]
// =====================================================================
__global__ void __launch_bounds__(256, 2) pre_gemm(
    const float* __restrict__ x,
    const float* __restrict__ tau_w,
    const float* __restrict__ tau_b,
    const float* __restrict__ mem_w,
    const float* __restrict__ mem_b)
{
    constexpr int Bk = 16;
    __shared__ float As[2][Bk][132];
    __shared__ float Bs[2][Bk][132];

    const int tid = threadIdx.x;
    const int m0 = blockIdx.y * 128;
    const int n0 = blockIdx.x * 128;

    const float* wbase;
    const float* bias;
    int rstride;
    float* outg;
    if (n0 < 512) { wbase = tau_w + (size_t)n0 * 1024; rstride = 1024; bias = tau_b + n0; outg = g_xp; }
    else          { wbase = mem_w + (size_t)(n0 - 512) * 512; rstride = 512; bias = mem_b + (n0 - 512); outg = g_m; }

    const int tm = tid >> 4;     // 0..15
    const int tn = tid & 15;     // 0..15

    // loader mapping: two chunks of 256
    const int lrow0 = (tid + 0)   >> 2;        // 0..63
    const int lkc0  = ((tid + 0) & 3) * 4;
    const int lrow1 = (tid + 256) >> 2;        // 64..127
    const int lkc1  = ((tid + 256) & 3) * 4;

    unsigned long long acc2[8][4];
#pragma unroll
    for (int i = 0; i < 8; i++)
#pragma unroll
        for (int p = 0; p < 4; p++) acc2[i][p] = 0ULL;

    float4 aR0, aR1, bR0, bR1;

    // prologue: load tile kk=0
    aR0 = *reinterpret_cast<const float4*>(&x[(size_t)(m0 + lrow0) * 512 + lkc0]);
    aR1 = *reinterpret_cast<const float4*>(&x[(size_t)(m0 + lrow1) * 512 + lkc1]);
    bR0 = *reinterpret_cast<const float4*>(&wbase[(size_t)lrow0 * rstride + lkc0]);
    bR1 = *reinterpret_cast<const float4*>(&wbase[(size_t)lrow1 * rstride + lkc1]);
    As[0][lkc0 + 0][lrow0] = aR0.x; As[0][lkc0 + 1][lrow0] = aR0.y;
    As[0][lkc0 + 2][lrow0] = aR0.z; As[0][lkc0 + 3][lrow0] = aR0.w;
    As[0][lkc1 + 0][lrow1] = aR1.x; As[0][lkc1 + 1][lrow1] = aR1.y;
    As[0][lkc1 + 2][lrow1] = aR1.z; As[0][lkc1 + 3][lrow1] = aR1.w;
    Bs[0][lkc0 + 0][lrow0] = bR0.x; Bs[0][lkc0 + 1][lrow0] = bR0.y;
    Bs[0][lkc0 + 2][lrow0] = bR0.z; Bs[0][lkc0 + 3][lrow0] = bR0.w;
    Bs[0][lkc1 + 0][lrow1] = bR1.x; Bs[0][lkc1 + 1][lrow1] = bR1.y;
    Bs[0][lkc1 + 2][lrow1] = bR1.z; Bs[0][lkc1 + 3][lrow1] = bR1.w;
    __syncthreads();

    for (int it = 0; it < 32; it++) {
        const int cur = it & 1;
        const int nxt = cur ^ 1;
        const bool hasNext = (it < 31);

        if (hasNext) {
            const int kk = (it + 1) * Bk;
            aR0 = *reinterpret_cast<const float4*>(&x[(size_t)(m0 + lrow0) * 512 + kk + lkc0]);
            aR1 = *reinterpret_cast<const float4*>(&x[(size_t)(m0 + lrow1) * 512 + kk + lkc1]);
            bR0 = *reinterpret_cast<const float4*>(&wbase[(size_t)lrow0 * rstride + kk + lkc0]);
            bR1 = *reinterpret_cast<const float4*>(&wbase[(size_t)lrow1 * rstride + kk + lkc1]);
        }

#pragma unroll
        for (int k = 0; k < Bk; k++) {
            float af[8];
            *reinterpret_cast<float4*>(&af[0]) = *reinterpret_cast<const float4*>(&As[cur][k][tm * 8]);
            *reinterpret_cast<float4*>(&af[4]) = *reinterpret_cast<const float4*>(&As[cur][k][tm * 8 + 4]);
            ulonglong2 b01 = *reinterpret_cast<const ulonglong2*>(&Bs[cur][k][tn * 8]);
            ulonglong2 b23 = *reinterpret_cast<const ulonglong2*>(&Bs[cur][k][tn * 8 + 4]);
#pragma unroll
            for (int i = 0; i < 8; i++) {
                unsigned long long a2 = pack2(af[i], af[i]);
                acc2[i][0] = fma2(a2, b01.x, acc2[i][0]);
                acc2[i][1] = fma2(a2, b01.y, acc2[i][1]);
                acc2[i][2] = fma2(a2, b23.x, acc2[i][2]);
                acc2[i][3] = fma2(a2, b23.y, acc2[i][3]);
            }
        }

        if (hasNext) {
            As[nxt][lkc0 + 0][lrow0] = aR0.x; As[nxt][lkc0 + 1][lrow0] = aR0.y;
            As[nxt][lkc0 + 2][lrow0] = aR0.z; As[nxt][lkc0 + 3][lrow0] = aR0.w;
            As[nxt][lkc1 + 0][lrow1] = aR1.x; As[nxt][lkc1 + 1][lrow1] = aR1.y;
            As[nxt][lkc1 + 2][lrow1] = aR1.z; As[nxt][lkc1 + 3][lrow1] = aR1.w;
            Bs[nxt][lkc0 + 0][lrow0] = bR0.x; Bs[nxt][lkc0 + 1][lrow0] = bR0.y;
            Bs[nxt][lkc0 + 2][lrow0] = bR0.z; Bs[nxt][lkc0 + 3][lrow0] = bR0.w;
            Bs[nxt][lkc1 + 0][lrow1] = bR1.x; Bs[nxt][lkc1 + 1][lrow1] = bR1.y;
            Bs[nxt][lkc1 + 2][lrow1] = bR1.z; Bs[nxt][lkc1 + 3][lrow1] = bR1.w;
        }
        __syncthreads();
    }

#pragma unroll
    for (int i = 0; i < 8; i++) {
        int r = m0 + tm * 8 + i;
        int b = r >> 10;
        int t = r & 1023;
        size_t rowoff = (size_t)t * BD + (size_t)b * DD;
#pragma unroll
        for (int p = 0; p < 4; p++) {
            float2 f = unpack2(acc2[i][p]);
            int n  = n0 + tn * 8 + 2 * p;
            outg[rowoff + ((n + 0) & 511)] = f.x + bias[tn * 8 + 2 * p + 0];
            outg[rowoff + ((n + 1) & 511)] = f.y + bias[tn * 8 + 2 * p + 1];
        }
    }
}

// =====================================================================
// Kernel 2: persistent scan, per-b-group sync + WARP-SELF-STAGING.
// 128 CTAs = 16 e-tiles(32e) x 8 b-groups(8b). tau_s slice
// [all 8 b][k0..k0+64) is written AND read only by warp kq ->
// staging needs only __syncwarp(), overlapped per warp.
// =====================================================================
__global__ void __launch_bounds__(256, 1) scan_kernel(
    const float* __restrict__ tau_w,
    const float* __restrict__ thr_p,
    float* __restrict__ out)
{
    __shared__ alignas(16) float tau_s[8 * 512];   // [b][k], warp-sliced by k
    __shared__ float red_s[8 * 8 * 32];            // [kq][bl][el] partials

    const int tid = threadIdx.x;
    const int eb = blockIdx.x & 15;        // e-tile
    const int bb = blockIdx.x >> 4;        // b-group
    const int e0 = eb * 32;
    const int b0 = bb * 8;

    const int kq = tid >> 5;               // warp id / k-slice of 64
    const int el = tid & 31;               // lane
    const int e  = e0 + el;
    const int k0 = kq * 64;

    // Wt[e, k0..k0+63] in registers as f32x2 (constant over steps)
    ulonglong2 wv2[16];
    {
        const ulonglong2* wrow = reinterpret_cast<const ulonglong2*>(
            tau_w + (size_t)e * 1024 + 512 + k0);
#pragma unroll
        for (int i = 0; i < 16; i++) wv2[i] = wrow[i];
    }

    // elementwise mapping: thread owns (pb, pe)
    const int pbl = tid >> 5;
    const int pel = tid & 31;
    const int pb = b0 + pbl;
    const int pe = e0 + pel;

    float v = 0.0f;
    const float thr = *thr_p;
    unsigned int* const cnt = &g_cnt[bb * 32];

    float* out_spk = out;
    float* out_tau = out + BTD;
    float* out_v   = out + BTD + BD;

    // tau_0 = 1 in our warp's slice (warp-private)
#pragma unroll
    for (int bl = 0; bl < 8; bl++) {
        float2 one = make_float2(1.0f, 1.0f);
        *reinterpret_cast<float2*>(&tau_s[bl * 512 + k0 + 2 * el]) = one;
    }
    __syncwarp();

    float xpv = __ldcs(&g_xp[(size_t)pb * DD + pe]);
    float mv  = __ldcs(&g_m [(size_t)pb * DD + pe]);

    for (int t = 0; t < TT; t++) {
        // ---- compute partial dots from own tau_s slice (broadcast LDS) ----
        unsigned long long acc2[8];
#pragma unroll
        for (int bl = 0; bl < 8; bl++) acc2[bl] = 0ULL;
#pragma unroll
        for (int jq = 0; jq < 16; jq++) {
            const ulonglong2 w2 = wv2[jq];
#pragma unroll
            for (int bl = 0; bl < 8; bl++) {
                const ulonglong2 t2 = *reinterpret_cast<const ulonglong2*>(
                    &tau_s[bl * 512 + k0 + jq * 4]);
                acc2[bl] = fma2(w2.x, t2.x, acc2[bl]);
                acc2[bl] = fma2(w2.y, t2.y, acc2[bl]);
            }
        }
#pragma unroll
        for (int bl = 0; bl < 8; bl++) {
            float2 f = unpack2(acc2[bl]);
            red_s[kq * 256 + bl * 32 + el] = f.x + f.y;
        }
        __syncthreads();                             // #1 partials ready

        // ---- reduce + new tau ----
        float z = xpv;
#pragma unroll
        for (int q = 0; q < 8; q++) z += red_s[q * 256 + pbl * 32 + pel];
        const float ta = 1.0f / (1.0f + expf(-z));

        if (t == TT - 1) {
            const float al = expf(-1.0f / (ta + 1e-6f));
            v = al * v + (1.0f - al) * mv;
            const float s = (v >= thr) ? 1.0f : 0.0f;
            __stcs(&out_spk[(size_t)pb * TT * DD + (size_t)t * DD + pe], s);
            v = v * (1.0f - s);
            out_tau[pb * DD + pe] = ta;
            out_v  [pb * DD + pe] = v;
            break;
        }

        const int nxt = (t + 1) & 1;
        __stcg(&g_tau[nxt][pb * DD + pe], ta);       // publish ASAP
        __syncthreads();                             // #2 all stores issued
        if (tid == 0) {
            __threadfence();
            atomicAdd(cnt, 1u);                      // arrive
        }

        // ---- overlap window: elementwise + prefetch ----
        const float al = expf(-1.0f / (ta + 1e-6f));
        v = al * v + (1.0f - al) * mv;
        const float s = (v >= thr) ? 1.0f : 0.0f;
        __stcs(&out_spk[(size_t)pb * TT * DD + (size_t)t * DD + pe], s);
        v = v * (1.0f - s);
        {
            size_t goff = (size_t)(t + 1) * BD + (size_t)pb * DD + pe;
            xpv = __ldcs(&g_xp[goff]);
            mv  = __ldcs(&g_m[goff]);
        }

        // ---- wait for group (16 CTAs) ----
        if (tid == 0) {
            const unsigned int target = 16u * (unsigned)(t + 1);
            while ((int)(ldacq(cnt) - target) < 0) {}
        }
        __syncthreads();                             // #3 release

        // ---- warp-self-stage own slice of tau_{t+1} (no block sync) ----
#pragma unroll
        for (int bl = 0; bl < 8; bl++) {
            const float2 v2 = __ldcg(reinterpret_cast<const float2*>(
                &g_tau[nxt][(b0 + bl) * 512 + k0 + 2 * el]));
            *reinterpret_cast<float2*>(&tau_s[bl * 512 + k0 + 2 * el]) = v2;
        }
        __syncwarp();
    }
}

// =====================================================================
extern "C" void kernel_launch(void* const* d_in, const int* in_sizes, int n_in,
                              void* d_out, int out_size)
{
    const float* x     = (const float*)d_in[0];
    const float* tau_w = (const float*)d_in[1];
    const float* tau_b = (const float*)d_in[2];
    const float* mem_w = (const float*)d_in[3];
    const float* mem_b = (const float*)d_in[4];
    const float* thr   = (const float*)d_in[5];
    float* out = (float*)d_out;

    init_kernel<<<1, 256>>>();
    dim3 ggrid(8, 512);                 // N tiles x M tiles
    pre_gemm<<<ggrid, 256>>>(x, tau_w, tau_b, mem_w, mem_b);
    scan_kernel<<<128, 256>>>(tau_w, thr, out);
}

// round 8
// speedup vs baseline: 1.7838x; 1.0019x over previous
#include <cuda_runtime.h>
#include <cuda_bf16.h>
#include <cstdint>

// Problem constants
#define BB 64
#define TT 1024
#define DD 512
#define BD (BB * DD)          // 32768
#define BTD ((size_t)BB * TT * DD)

// ---------------- scratch (no allocations allowed) ----------------
__device__ float g_xp[(size_t)TT * BB * DD];   // xproj, layout [t][b][e]
__device__ float g_m [(size_t)TT * BB * DD];   // m,     layout [t][b][e]
__device__ float g_tau[2][BD];                 // ping-pong tau state [b][e]
__device__ unsigned int g_cnt[8 * 32];         // per-b-group barrier counters (128B apart)

// ---------------- f32x2 packed-FMA helpers ----------------
__device__ __forceinline__ unsigned long long fma2(unsigned long long a,
                                                   unsigned long long b,
                                                   unsigned long long c)
{
    unsigned long long d;
    asm("fma.rn.f32x2 %0, %1, %2, %3;" : "=l"(d) : "l"(a), "l"(b), "l"(c));
    return d;
}
__device__ __forceinline__ unsigned long long pack2(float lo, float hi)
{
    unsigned long long r;
    asm("mov.b64 %0, {%1, %2};" : "=l"(r) : "f"(lo), "f"(hi));
    return r;
}
__device__ __forceinline__ float2 unpack2(unsigned long long v)
{
    float2 f;
    asm("mov.b64 {%0, %1}, %2;" : "=f"(f.x), "=f"(f.y) : "l"(v));
    return f;
}
__device__ __forceinline__ unsigned int ldacq(const unsigned int* p)
{
    unsigned int v;
    asm volatile("ld.acquire.gpu.u32 %0, [%1];" : "=r"(v) : "l"(p));
    return v;
}

// =====================================================================
// Kernel 0: init (per-launch reset of group barrier counters)
// =====================================================================
__global__ void __launch_bounds__(256) init_kernel()
{
    if (threadIdx.x < 8 * 32) g_cnt[threadIdx.x] = 0u;
}

// =====================================================================
// Kernel 1: fused precompute GEMM, double-buffered smem (1 sync/iter)
//   out[r, n] = sum_k x[r,k] * W[n,k] + bias[n]
//   n <  512 : W = Wx  = tau_w[n, 0:512]   -> g_xp
//   n >= 512 : W = mem_w[n-512, :]         -> g_m
//   row r = b*T + t ; output written at [t][b][e]
// =====================================================================
__global__ void __launch_bounds__(256, 2) pre_gemm(
    const float* __restrict__ x,
    const float* __restrict__ tau_w,
    const float* __restrict__ tau_b,
    const float* __restrict__ mem_w,
    const float* __restrict__ mem_b)
{
    constexpr int Bk = 16;
    __shared__ float As[2][Bk][132];
    __shared__ float Bs[2][Bk][132];

    const int tid = threadIdx.x;
    const int m0 = blockIdx.y * 128;
    const int n0 = blockIdx.x * 128;

    const float* wbase;
    const float* bias;
    int rstride;
    float* outg;
    if (n0 < 512) { wbase = tau_w + (size_t)n0 * 1024; rstride = 1024; bias = tau_b + n0; outg = g_xp; }
    else          { wbase = mem_w + (size_t)(n0 - 512) * 512; rstride = 512; bias = mem_b + (n0 - 512); outg = g_m; }

    const int tm = tid >> 4;     // 0..15
    const int tn = tid & 15;     // 0..15

    // loader mapping: two chunks of 256
    const int lrow0 = (tid + 0)   >> 2;        // 0..63
    const int lkc0  = ((tid + 0) & 3) * 4;
    const int lrow1 = (tid + 256) >> 2;        // 64..127
    const int lkc1  = ((tid + 256) & 3) * 4;

    unsigned long long acc2[8][4];
#pragma unroll
    for (int i = 0; i < 8; i++)
#pragma unroll
        for (int p = 0; p < 4; p++) acc2[i][p] = 0ULL;

    float4 aR0, aR1, bR0, bR1;

    // prologue: load tile kk=0
    aR0 = *reinterpret_cast<const float4*>(&x[(size_t)(m0 + lrow0) * 512 + lkc0]);
    aR1 = *reinterpret_cast<const float4*>(&x[(size_t)(m0 + lrow1) * 512 + lkc1]);
    bR0 = *reinterpret_cast<const float4*>(&wbase[(size_t)lrow0 * rstride + lkc0]);
    bR1 = *reinterpret_cast<const float4*>(&wbase[(size_t)lrow1 * rstride + lkc1]);
    As[0][lkc0 + 0][lrow0] = aR0.x; As[0][lkc0 + 1][lrow0] = aR0.y;
    As[0][lkc0 + 2][lrow0] = aR0.z; As[0][lkc0 + 3][lrow0] = aR0.w;
    As[0][lkc1 + 0][lrow1] = aR1.x; As[0][lkc1 + 1][lrow1] = aR1.y;
    As[0][lkc1 + 2][lrow1] = aR1.z; As[0][lkc1 + 3][lrow1] = aR1.w;
    Bs[0][lkc0 + 0][lrow0] = bR0.x; Bs[0][lkc0 + 1][lrow0] = bR0.y;
    Bs[0][lkc0 + 2][lrow0] = bR0.z; Bs[0][lkc0 + 3][lrow0] = bR0.w;
    Bs[0][lkc1 + 0][lrow1] = bR1.x; Bs[0][lkc1 + 1][lrow1] = bR1.y;
    Bs[0][lkc1 + 2][lrow1] = bR1.z; Bs[0][lkc1 + 3][lrow1] = bR1.w;
    __syncthreads();

    for (int it = 0; it < 32; it++) {
        const int cur = it & 1;
        const int nxt = cur ^ 1;
        const bool hasNext = (it < 31);

        if (hasNext) {
            const int kk = (it + 1) * Bk;
            aR0 = *reinterpret_cast<const float4*>(&x[(size_t)(m0 + lrow0) * 512 + kk + lkc0]);
            aR1 = *reinterpret_cast<const float4*>(&x[(size_t)(m0 + lrow1) * 512 + kk + lkc1]);
            bR0 = *reinterpret_cast<const float4*>(&wbase[(size_t)lrow0 * rstride + kk + lkc0]);
            bR1 = *reinterpret_cast<const float4*>(&wbase[(size_t)lrow1 * rstride + kk + lkc1]);
        }

#pragma unroll
        for (int k = 0; k < Bk; k++) {
            float af[8];
            *reinterpret_cast<float4*>(&af[0]) = *reinterpret_cast<const float4*>(&As[cur][k][tm * 8]);
            *reinterpret_cast<float4*>(&af[4]) = *reinterpret_cast<const float4*>(&As[cur][k][tm * 8 + 4]);
            ulonglong2 b01 = *reinterpret_cast<const ulonglong2*>(&Bs[cur][k][tn * 8]);
            ulonglong2 b23 = *reinterpret_cast<const ulonglong2*>(&Bs[cur][k][tn * 8 + 4]);
#pragma unroll
            for (int i = 0; i < 8; i++) {
                unsigned long long a2 = pack2(af[i], af[i]);
                acc2[i][0] = fma2(a2, b01.x, acc2[i][0]);
                acc2[i][1] = fma2(a2, b01.y, acc2[i][1]);
                acc2[i][2] = fma2(a2, b23.x, acc2[i][2]);
                acc2[i][3] = fma2(a2, b23.y, acc2[i][3]);
            }
        }

        if (hasNext) {
            As[nxt][lkc0 + 0][lrow0] = aR0.x; As[nxt][lkc0 + 1][lrow0] = aR0.y;
            As[nxt][lkc0 + 2][lrow0] = aR0.z; As[nxt][lkc0 + 3][lrow0] = aR0.w;
            As[nxt][lkc1 + 0][lrow1] = aR1.x; As[nxt][lkc1 + 1][lrow1] = aR1.y;
            As[nxt][lkc1 + 2][lrow1] = aR1.z; As[nxt][lkc1 + 3][lrow1] = aR1.w;
            Bs[nxt][lkc0 + 0][lrow0] = bR0.x; Bs[nxt][lkc0 + 1][lrow0] = bR0.y;
            Bs[nxt][lkc0 + 2][lrow0] = bR0.z; Bs[nxt][lkc0 + 3][lrow0] = bR0.w;
            Bs[nxt][lkc1 + 0][lrow1] = bR1.x; Bs[nxt][lkc1 + 1][lrow1] = bR1.y;
            Bs[nxt][lkc1 + 2][lrow1] = bR1.z; Bs[nxt][lkc1 + 3][lrow1] = bR1.w;
        }
        __syncthreads();
    }

#pragma unroll
    for (int i = 0; i < 8; i++) {
        int r = m0 + tm * 8 + i;
        int b = r >> 10;
        int t = r & 1023;
        size_t rowoff = (size_t)t * BD + (size_t)b * DD;
#pragma unroll
        for (int p = 0; p < 4; p++) {
            float2 f = unpack2(acc2[i][p]);
            int n  = n0 + tn * 8 + 2 * p;
            outg[rowoff + ((n + 0) & 511)] = f.x + bias[tn * 8 + 2 * p + 0];
            outg[rowoff + ((n + 1) & 511)] = f.y + bias[tn * 8 + 2 * p + 1];
        }
    }
}

// =====================================================================
// Kernel 2: persistent scan, per-b-group sync + WARP-SELF-STAGING.
// 128 CTAs = 16 e-tiles(32e) x 8 b-groups(8b). tau_s slice
// [all 8 b][k0..k0+64) is written AND read only by warp kq ->
// staging needs only __syncwarp(), overlapped per warp.
// =====================================================================
__global__ void __launch_bounds__(256, 1) scan_kernel(
    const float* __restrict__ tau_w,
    const float* __restrict__ thr_p,
    float* __restrict__ out)
{
    __shared__ alignas(16) float tau_s[8 * 512];   // [b][k], warp-sliced by k
    __shared__ float red_s[8 * 8 * 32];            // [kq][bl][el] partials

    const int tid = threadIdx.x;
    const int eb = blockIdx.x & 15;        // e-tile
    const int bb = blockIdx.x >> 4;        // b-group
    const int e0 = eb * 32;
    const int b0 = bb * 8;

    const int kq = tid >> 5;               // warp id / k-slice of 64
    const int el = tid & 31;               // lane
    const int e  = e0 + el;
    const int k0 = kq * 64;

    // Wt[e, k0..k0+63] in registers as f32x2 (constant over steps)
    ulonglong2 wv2[16];
    {
        const ulonglong2* wrow = reinterpret_cast<const ulonglong2*>(
            tau_w + (size_t)e * 1024 + 512 + k0);
#pragma unroll
        for (int i = 0; i < 16; i++) wv2[i] = wrow[i];
    }

    // elementwise mapping: thread owns (pb, pe)
    const int pbl = tid >> 5;
    const int pel = tid & 31;
    const int pb = b0 + pbl;
    const int pe = e0 + pel;

    float v = 0.0f;
    const float thr = *thr_p;
    unsigned int* const cnt = &g_cnt[bb * 32];

    float* out_spk = out;
    float* out_tau = out + BTD;
    float* out_v   = out + BTD + BD;

    // tau_0 = 1 in our warp's slice (warp-private)
#pragma unroll
    for (int bl = 0; bl < 8; bl++) {
        float2 one = make_float2(1.0f, 1.0f);
        *reinterpret_cast<float2*>(&tau_s[bl * 512 + k0 + 2 * el]) = one;
    }
    __syncwarp();

    float xpv = __ldcs(&g_xp[(size_t)pb * DD + pe]);
    float mv  = __ldcs(&g_m [(size_t)pb * DD + pe]);

    for (int t = 0; t < TT; t++) {
        // ---- compute partial dots from own tau_s slice (broadcast LDS) ----
        unsigned long long acc2[8];
#pragma unroll
        for (int bl = 0; bl < 8; bl++) acc2[bl] = 0ULL;
#pragma unroll
        for (int jq = 0; jq < 16; jq++) {
            const ulonglong2 w2 = wv2[jq];
#pragma unroll
            for (int bl = 0; bl < 8; bl++) {
                const ulonglong2 t2 = *reinterpret_cast<const ulonglong2*>(
                    &tau_s[bl * 512 + k0 + jq * 4]);
                acc2[bl] = fma2(w2.x, t2.x, acc2[bl]);
                acc2[bl] = fma2(w2.y, t2.y, acc2[bl]);
            }
        }
#pragma unroll
        for (int bl = 0; bl < 8; bl++) {
            float2 f = unpack2(acc2[bl]);
            red_s[kq * 256 + bl * 32 + el] = f.x + f.y;
        }
        __syncthreads();                             // #1 partials ready

        // ---- reduce + new tau ----
        float z = xpv;
#pragma unroll
        for (int q = 0; q < 8; q++) z += red_s[q * 256 + pbl * 32 + pel];
        const float ta = 1.0f / (1.0f + expf(-z));

        if (t == TT - 1) {
            const float al = expf(-1.0f / (ta + 1e-6f));
            v = al * v + (1.0f - al) * mv;
            const float s = (v >= thr) ? 1.0f : 0.0f;
            __stcs(&out_spk[(size_t)pb * TT * DD + (size_t)t * DD + pe], s);
            v = v * (1.0f - s);
            out_tau[pb * DD + pe] = ta;
            out_v  [pb * DD + pe] = v;
            break;
        }

        const int nxt = (t + 1) & 1;
        __stcg(&g_tau[nxt][pb * DD + pe], ta);       // publish ASAP
        __syncthreads();                             // #2 all stores issued
        if (tid == 0) {
            __threadfence();
            atomicAdd(cnt, 1u);                      // arrive
        }

        // ---- overlap window: elementwise + prefetch ----
        const float al = expf(-1.0f / (ta + 1e-6f));
        v = al * v + (1.0f - al) * mv;
        const float s = (v >= thr) ? 1.0f : 0.0f;
        __stcs(&out_spk[(size_t)pb * TT * DD + (size_t)t * DD + pe], s);
        v = v * (1.0f - s);
        {
            size_t goff = (size_t)(t + 1) * BD + (size_t)pb * DD + pe;
            xpv = __ldcs(&g_xp[goff]);
            mv  = __ldcs(&g_m[goff]);
        }

        // ---- wait for group (16 CTAs) ----
        if (tid == 0) {
            const unsigned int target = 16u * (unsigned)(t + 1);
            while ((int)(ldacq(cnt) - target) < 0) {}
        }
        __syncthreads();                             // #3 release

        // ---- warp-self-stage own slice of tau_{t+1} (no block sync) ----
#pragma unroll
        for (int bl = 0; bl < 8; bl++) {
            const float2 v2 = __ldcg(reinterpret_cast<const float2*>(
                &g_tau[nxt][(b0 + bl) * 512 + k0 + 2 * el]));
            *reinterpret_cast<float2*>(&tau_s[bl * 512 + k0 + 2 * el]) = v2;
        }
        __syncwarp();
    }
}

// =====================================================================
extern "C" void kernel_launch(void* const* d_in, const int* in_sizes, int n_in,
                              void* d_out, int out_size)
{
    const float* x     = (const float*)d_in[0];
    const float* tau_w = (const float*)d_in[1];
    const float* tau_b = (const float*)d_in[2];
    const float* mem_w = (const float*)d_in[3];
    const float* mem_b = (const float*)d_in[4];
    const float* thr   = (const float*)d_in[5];
    float* out = (float*)d_out;

    init_kernel<<<1, 256>>>();
    dim3 ggrid(8, 512);                 // N tiles x M tiles
    pre_gemm<<<ggrid, 256>>>(x, tau_w, tau_b, mem_w, mem_b);
    scan_kernel<<<128, 256>>>(tau_w, thr, out);
}